// round 1
// baseline (speedup 1.0000x reference)
#include <cuda_runtime.h>

// Problem constants
constexpr int NB = 32;    // batch
constexpr int NT = 1024;  // tokens (32x32)
constexpr int NF = 768;   // features
constexpr int NS = 16;    // splits per batch in pass C
constexpr int TOK_PER_BLK  = NT / NS;       // 64 tokens per block
constexpr int TOK_PER_WARP = TOK_PER_BLK/8; // 8 tokens per warp

// Scratch (device globals — no allocations allowed)
__device__ float g_rnorm[NB * NT];
__device__ float g_p1[NB * NT];
__device__ float g_q[NB * NF];            // normalized argmax token per batch
__device__ float g_part[NB * NS * NF];    // split partial weighted sums
__device__ float g_upart[NB * NS];        // split partial weight sums

// ---------------------------------------------------------------------------
// Kernel A: one warp per token. Computes ||tok||, tok.fc_w0, tok.fc_w1
// -> rnorm, p1 (= softmax(logits)[1] = 1/(1+exp(l0-l1)))
// ---------------------------------------------------------------------------
__global__ __launch_bounds__(256) void kA(const float* __restrict__ x,
                                          const float* __restrict__ fc_w,
                                          const float* __restrict__ fc_b) {
    const int warp = threadIdx.x >> 5;
    const int lane = threadIdx.x & 31;
    const int g = blockIdx.x * 8 + warp;  // global token id in [0, NB*NT)

    const float4* tok = reinterpret_cast<const float4*>(x + (size_t)g * NF);
    const float4* w0  = reinterpret_cast<const float4*>(fc_w);
    const float4* w1  = reinterpret_cast<const float4*>(fc_w + NF);

    float nrm = 0.f, d0 = 0.f, d1 = 0.f;
#pragma unroll
    for (int i = 0; i < 6; i++) {
        float4 v = tok[lane + 32 * i];
        float4 a = __ldg(&w0[lane + 32 * i]);
        float4 b = __ldg(&w1[lane + 32 * i]);
        nrm += v.x * v.x + v.y * v.y + v.z * v.z + v.w * v.w;
        d0  += v.x * a.x + v.y * a.y + v.z * a.z + v.w * a.w;
        d1  += v.x * b.x + v.y * b.y + v.z * b.z + v.w * b.w;
    }
#pragma unroll
    for (int o = 16; o; o >>= 1) {
        nrm += __shfl_xor_sync(0xffffffffu, nrm, o);
        d0  += __shfl_xor_sync(0xffffffffu, d0, o);
        d1  += __shfl_xor_sync(0xffffffffu, d1, o);
    }
    if (lane == 0) {
        g_rnorm[g] = rsqrtf(nrm);
        float l0 = d0 + fc_b[0];
        float l1 = d1 + fc_b[1];
        g_p1[g] = 1.f / (1.f + expf(l0 - l1));
    }
}

// ---------------------------------------------------------------------------
// Kernel B: per-batch argmax of p1 (first-max tiebreak, matches jnp.argmax),
// then write q = tok[idx] * rnorm[idx].
// ---------------------------------------------------------------------------
__global__ __launch_bounds__(1024) void kB(const float* __restrict__ x) {
    __shared__ float sv[NT];
    __shared__ int   si[NT];
    const int b = blockIdx.x;
    const int t = threadIdx.x;

    sv[t] = g_p1[b * NT + t];
    si[t] = t;
    __syncthreads();
#pragma unroll
    for (int o = 512; o; o >>= 1) {
        if (t < o) {
            float v2 = sv[t + o];
            int   i2 = si[t + o];
            if (v2 > sv[t] || (v2 == sv[t] && i2 < si[t])) { sv[t] = v2; si[t] = i2; }
        }
        __syncthreads();
    }
    const int idx = si[0];
    const float rn = g_rnorm[b * NT + idx];
    const float* tok = x + ((size_t)b * NT + idx) * NF;
    if (t < NF) g_q[b * NF + t] = tok[t] * rn;
}

// ---------------------------------------------------------------------------
// Kernel C: streaming weighted-sum pass. grid = (NS, NB), 256 threads.
// Each warp handles 8 tokens: s = q . tok * rnorm_t ; u = exp(s) * p1_t ;
// accumulate u*tok (lane-partitioned, 24 floats/lane) and u.
// Deterministic: warp-staggered shared reduction, no atomics.
// ---------------------------------------------------------------------------
__global__ __launch_bounds__(256) void kC(const float* __restrict__ x) {
    const int b    = blockIdx.y;
    const int sp   = blockIdx.x;
    const int warp = threadIdx.x >> 5;
    const int lane = threadIdx.x & 31;

    __shared__ float4 q4s[NF / 4];   // 3 KB
    __shared__ float  sacc[NF];      // 3 KB
    __shared__ float  sU;

    const float4* q4 = reinterpret_cast<const float4*>(g_q + b * NF);
    for (int i = threadIdx.x; i < NF / 4; i += 256) q4s[i] = q4[i];
    for (int i = threadIdx.x; i < NF; i += 256) sacc[i] = 0.f;
    if (threadIdx.x == 0) sU = 0.f;
    __syncthreads();

    float4 acc[6];
#pragma unroll
    for (int i = 0; i < 6; i++) acc[i] = make_float4(0.f, 0.f, 0.f, 0.f);
    float u_sum = 0.f;

    const int t0 = sp * TOK_PER_BLK + warp * TOK_PER_WARP;
#pragma unroll 2
    for (int tt = 0; tt < TOK_PER_WARP; tt++) {
        const int t = t0 + tt;
        const float4* tok = reinterpret_cast<const float4*>(x + ((size_t)b * NT + t) * NF);
        float4 v[6];
        float s = 0.f;
#pragma unroll
        for (int i = 0; i < 6; i++) {
            v[i] = tok[lane + 32 * i];
            float4 q = q4s[lane + 32 * i];
            s += v[i].x * q.x + v[i].y * q.y + v[i].z * q.z + v[i].w * q.w;
        }
#pragma unroll
        for (int o = 16; o; o >>= 1) s += __shfl_xor_sync(0xffffffffu, s, o);
        const float u = expf(s * g_rnorm[b * NT + t]) * g_p1[b * NT + t];
        u_sum += u;
#pragma unroll
        for (int i = 0; i < 6; i++) {
            acc[i].x += u * v[i].x;
            acc[i].y += u * v[i].y;
            acc[i].z += u * v[i].z;
            acc[i].w += u * v[i].w;
        }
    }

    // Deterministic cross-warp reduction: warps add to shared in fixed order.
    for (int w = 0; w < 8; w++) {
        if (warp == w) {
#pragma unroll
            for (int i = 0; i < 6; i++) {
                const int f = 4 * (lane + 32 * i);
                sacc[f + 0] += acc[i].x;
                sacc[f + 1] += acc[i].y;
                sacc[f + 2] += acc[i].z;
                sacc[f + 3] += acc[i].w;
            }
            if (lane == 0) sU += u_sum;
        }
        __syncthreads();
    }

    float* part = g_part + ((size_t)b * NS + sp) * NF;
    for (int i = threadIdx.x; i < NF; i += 256) part[i] = sacc[i];
    if (threadIdx.x == 0) g_upart[b * NS + sp] = sU;
}

// ---------------------------------------------------------------------------
// Kernel D: reduce splits, normalize, final 768x2 GEMV + bias.
// ---------------------------------------------------------------------------
__global__ __launch_bounds__(256) void kD(const float* __restrict__ fc_final_w,
                                          const float* __restrict__ fc_final_b,
                                          float* __restrict__ out) {
    __shared__ float red0[256], red1[256];
    const int b = blockIdx.x;
    const int t = threadIdx.x;

    float U = 0.f;
#pragma unroll
    for (int s = 0; s < NS; s++) U += g_upart[b * NS + s];

    float d0 = 0.f, d1 = 0.f;
    for (int f = t; f < NF; f += 256) {
        float a = 0.f;
#pragma unroll
        for (int s = 0; s < NS; s++) a += g_part[((size_t)b * NS + s) * NF + f];
        d0 += a * fc_final_w[f];
        d1 += a * fc_final_w[NF + f];
    }
    red0[t] = d0; red1[t] = d1;
    __syncthreads();
#pragma unroll
    for (int o = 128; o; o >>= 1) {
        if (t < o) { red0[t] += red0[t + o]; red1[t] += red1[t + o]; }
        __syncthreads();
    }
    if (t == 0) {
        const float invU = 1.f / U;
        out[b * 2 + 0] = red0[0] * invU + fc_final_b[0];
        out[b * 2 + 1] = red1[0] * invU + fc_final_b[1];
    }
}

// ---------------------------------------------------------------------------
extern "C" void kernel_launch(void* const* d_in, const int* in_sizes, int n_in,
                              void* d_out, int out_size) {
    const float* x          = (const float*)d_in[0];
    const float* fc_w       = (const float*)d_in[1];
    const float* fc_b       = (const float*)d_in[2];
    const float* fc_final_w = (const float*)d_in[3];
    const float* fc_final_b = (const float*)d_in[4];
    float* out = (float*)d_out;

    kA<<<NB * NT / 8, 256>>>(x, fc_w, fc_b);
    kB<<<NB, 1024>>>(x);
    dim3 gridC(NS, NB);
    kC<<<gridC, 256>>>(x);
    kD<<<NB, 256>>>(fc_final_w, fc_final_b, out);
}

// round 3
// speedup vs baseline: 1.1558x; 1.1558x over previous
#include <cuda_runtime.h>

// Problem constants
constexpr int NB = 32;    // batch
constexpr int NT = 1024;  // tokens (32x32)
constexpr int NF = 768;   // features
constexpr int NS = 16;    // splits per batch in pass C
constexpr int TOK_PER_BLK  = NT / NS;       // 64 tokens per block
constexpr int TOK_PER_WARP = TOK_PER_BLK/8; // 8 tokens per warp

// Scratch (device globals — no allocations allowed)
__device__ float g_rnorm[NB * NT];
__device__ float g_p1[NB * NT];
__device__ float g_q[NB * NF];          // normalized argmax token per batch
__device__ float g_d0[NB * NS];         // split partial: (sum u*tok) . fc_final_w0
__device__ float g_d1[NB * NS];         // split partial: (sum u*tok) . fc_final_w1
__device__ float g_u [NB * NS];         // split partial: sum u

// ---------------------------------------------------------------------------
// Kernel A: one warp per token. Computes ||tok||, tok.fc_w0, tok.fc_w1
// -> rnorm, p1 (= softmax(logits)[1] = 1/(1+exp(l0-l1)))
// ---------------------------------------------------------------------------
__global__ __launch_bounds__(256) void kA(const float* __restrict__ x,
                                          const float* __restrict__ fc_w,
                                          const float* __restrict__ fc_b) {
    const int warp = threadIdx.x >> 5;
    const int lane = threadIdx.x & 31;
    const int g = blockIdx.x * 8 + warp;  // global token id in [0, NB*NT)

    const float4* tok = reinterpret_cast<const float4*>(x + (size_t)g * NF);
    const float4* w0  = reinterpret_cast<const float4*>(fc_w);
    const float4* w1  = reinterpret_cast<const float4*>(fc_w + NF);

    float nrm = 0.f, d0 = 0.f, d1 = 0.f;
#pragma unroll
    for (int i = 0; i < 6; i++) {
        float4 v = tok[lane + 32 * i];
        float4 a = __ldg(&w0[lane + 32 * i]);
        float4 b = __ldg(&w1[lane + 32 * i]);
        nrm += v.x * v.x + v.y * v.y + v.z * v.z + v.w * v.w;
        d0  += v.x * a.x + v.y * a.y + v.z * a.z + v.w * a.w;
        d1  += v.x * b.x + v.y * b.y + v.z * b.z + v.w * b.w;
    }
#pragma unroll
    for (int o = 16; o; o >>= 1) {
        nrm += __shfl_xor_sync(0xffffffffu, nrm, o);
        d0  += __shfl_xor_sync(0xffffffffu, d0, o);
        d1  += __shfl_xor_sync(0xffffffffu, d1, o);
    }
    if (lane == 0) {
        g_rnorm[g] = rsqrtf(nrm);
        float l0 = d0 + fc_b[0];
        float l1 = d1 + fc_b[1];
        g_p1[g] = 1.f / (1.f + expf(l0 - l1));
    }
}

// ---------------------------------------------------------------------------
// Kernel B: per-batch argmax of p1 (first-max tiebreak, matches jnp.argmax),
// then write q = tok[idx] * rnorm[idx].
// ---------------------------------------------------------------------------
__global__ __launch_bounds__(1024) void kB(const float* __restrict__ x) {
    __shared__ float sv[NT];
    __shared__ int   si[NT];
    const int b = blockIdx.x;
    const int t = threadIdx.x;

    sv[t] = g_p1[b * NT + t];
    si[t] = t;
    __syncthreads();
#pragma unroll
    for (int o = 512; o; o >>= 1) {
        if (t < o) {
            float v2 = sv[t + o];
            int   i2 = si[t + o];
            if (v2 > sv[t] || (v2 == sv[t] && i2 < si[t])) { sv[t] = v2; si[t] = i2; }
        }
        __syncthreads();
    }
    const int idx = si[0];
    const float rn = g_rnorm[b * NT + idx];
    const float* tok = x + ((size_t)b * NT + idx) * NF;
    if (t < NF) g_q[b * NF + t] = tok[t] * rn;
}

// ---------------------------------------------------------------------------
// Kernel C: streaming weighted-sum pass. grid = (NS, NB), 256 threads.
// Each warp handles 8 tokens: s = q . tok * rnorm_t ; u = exp(s) * p1_t ;
// accumulate u*tok in registers (24 floats/lane). Epilogue projects the
// register accumulator directly onto fc_final_w -> only 3 scalars out.
// NOTE: u_sum is lane-REPLICATED (s fully reduced before exp), so it must
// NOT be shuffle-reduced — take lane 0's value only.
// ---------------------------------------------------------------------------
__global__ __launch_bounds__(256) void kC(const float* __restrict__ x,
                                          const float* __restrict__ fc_final_w) {
    const int b    = blockIdx.y;
    const int sp   = blockIdx.x;
    const int warp = threadIdx.x >> 5;
    const int lane = threadIdx.x & 31;

    __shared__ float4 q4s[NF / 4];   // 3 KB
    __shared__ float  s0[8], s1[8], su[8];

    const float4* q4 = reinterpret_cast<const float4*>(g_q + b * NF);
    for (int i = threadIdx.x; i < NF / 4; i += 256) q4s[i] = q4[i];
    __syncthreads();

    float4 acc[6];
#pragma unroll
    for (int i = 0; i < 6; i++) acc[i] = make_float4(0.f, 0.f, 0.f, 0.f);
    float u_sum = 0.f;

    const int t0 = sp * TOK_PER_BLK + warp * TOK_PER_WARP;
#pragma unroll 2
    for (int tt = 0; tt < TOK_PER_WARP; tt++) {
        const int t = t0 + tt;
        const float rn = g_rnorm[b * NT + t];
        const float p1 = g_p1[b * NT + t];
        const float4* tok = reinterpret_cast<const float4*>(x + ((size_t)b * NT + t) * NF);
        float4 v[6];
        float s = 0.f;
#pragma unroll
        for (int i = 0; i < 6; i++) {
            v[i] = tok[lane + 32 * i];
            float4 q = q4s[lane + 32 * i];
            s += v[i].x * q.x + v[i].y * q.y + v[i].z * q.z + v[i].w * q.w;
        }
#pragma unroll
        for (int o = 16; o; o >>= 1) s += __shfl_xor_sync(0xffffffffu, s, o);
        const float u = expf(s * rn) * p1;   // identical in every lane
        u_sum += u;
#pragma unroll
        for (int i = 0; i < 6; i++) {
            acc[i].x += u * v[i].x;
            acc[i].y += u * v[i].y;
            acc[i].z += u * v[i].z;
            acc[i].w += u * v[i].w;
        }
    }

    // Project register accumulator onto fc_final_w (lane owns f = 4*(lane+32i)+0..3)
    const float4* fw0 = reinterpret_cast<const float4*>(fc_final_w);
    const float4* fw1 = reinterpret_cast<const float4*>(fc_final_w + NF);
    float d0 = 0.f, d1 = 0.f;
#pragma unroll
    for (int i = 0; i < 6; i++) {
        float4 a = __ldg(&fw0[lane + 32 * i]);
        float4 c = __ldg(&fw1[lane + 32 * i]);
        d0 += acc[i].x * a.x + acc[i].y * a.y + acc[i].z * a.z + acc[i].w * a.w;
        d1 += acc[i].x * c.x + acc[i].y * c.y + acc[i].z * c.z + acc[i].w * c.w;
    }
#pragma unroll
    for (int o = 16; o; o >>= 1) {
        d0 += __shfl_xor_sync(0xffffffffu, d0, o);
        d1 += __shfl_xor_sync(0xffffffffu, d1, o);
    }
    if (lane == 0) { s0[warp] = d0; s1[warp] = d1; su[warp] = u_sum; }
    __syncthreads();
    if (threadIdx.x == 0) {
        float D0 = 0.f, D1 = 0.f, U = 0.f;
#pragma unroll
        for (int w = 0; w < 8; w++) { D0 += s0[w]; D1 += s1[w]; U += su[w]; }
        g_d0[b * NS + sp] = D0;
        g_d1[b * NS + sp] = D1;
        g_u [b * NS + sp] = U;
    }
}

// ---------------------------------------------------------------------------
// Kernel D: one block, warp per batch. Reduce 16 split scalars, normalize,
// add bias.
// ---------------------------------------------------------------------------
__global__ __launch_bounds__(1024) void kD(const float* __restrict__ fc_final_b,
                                           float* __restrict__ out) {
    const int b    = threadIdx.x >> 5;   // 32 warps = 32 batches
    const int lane = threadIdx.x & 31;

    float d0 = 0.f, d1 = 0.f, u = 0.f;
    if (lane < NS) {
        d0 = g_d0[b * NS + lane];
        d1 = g_d1[b * NS + lane];
        u  = g_u [b * NS + lane];
    }
#pragma unroll
    for (int o = 8; o; o >>= 1) {
        d0 += __shfl_xor_sync(0xffffffffu, d0, o);
        d1 += __shfl_xor_sync(0xffffffffu, d1, o);
        u  += __shfl_xor_sync(0xffffffffu, u, o);
    }
    if (lane == 0) {
        const float invU = 1.f / u;
        out[b * 2 + 0] = d0 * invU + fc_final_b[0];
        out[b * 2 + 1] = d1 * invU + fc_final_b[1];
    }
}

// ---------------------------------------------------------------------------
extern "C" void kernel_launch(void* const* d_in, const int* in_sizes, int n_in,
                              void* d_out, int out_size) {
    const float* x          = (const float*)d_in[0];
    const float* fc_w       = (const float*)d_in[1];
    const float* fc_b       = (const float*)d_in[2];
    const float* fc_final_w = (const float*)d_in[3];
    const float* fc_final_b = (const float*)d_in[4];
    float* out = (float*)d_out;

    kA<<<NB * NT / 8, 256>>>(x, fc_w, fc_b);
    kB<<<NB, 1024>>>(x);
    dim3 gridC(NS, NB);
    kC<<<gridC, 256>>>(x, fc_final_w);
    kD<<<1, 1024>>>(fc_final_b, out);
}